// round 1
// baseline (speedup 1.0000x reference)
#include <cuda_runtime.h>
#include <cuda_bf16.h>
#include <cstdint>

// Problem dims (fixed by the reference)
#define M_TOT 8192   // B*S = 4*2048
#define N_TOT 4096   // OUT
#define K_TOT 4096   // IN

// ---------------------------------------------------------------------------
// Scratch (device globals — no runtime allocation allowed)
// x split into bf16 hi/lo; W_total = (int4-8) + ortho/scale split into hi/lo.
// out = scale[n] * sum_k ( x_hi*W_hi + x_lo*W_hi + x_hi*W_lo )
// ---------------------------------------------------------------------------
static __device__ __nv_bfloat16 g_Ahi[(size_t)M_TOT * K_TOT];
static __device__ __nv_bfloat16 g_Alo[(size_t)M_TOT * K_TOT];
static __device__ __nv_bfloat16 g_Whi[(size_t)N_TOT * K_TOT];
static __device__ __nv_bfloat16 g_Wlo[(size_t)N_TOT * K_TOT];

// ---------------------------------------------------------------------------
// Prep 1: split x (fp32) into hi/lo bf16. 8 floats per thread.
// ---------------------------------------------------------------------------
__global__ void prep_x_kernel(const float* __restrict__ x) {
    size_t i = (size_t)blockIdx.x * blockDim.x + threadIdx.x; // vec-8 index
    if (i >= ((size_t)M_TOT * K_TOT) / 8) return;
    const float4* xv = reinterpret_cast<const float4*>(x);
    float4 v0 = xv[i * 2 + 0];
    float4 v1 = xv[i * 2 + 1];
    float f[8] = {v0.x, v0.y, v0.z, v0.w, v1.x, v1.y, v1.z, v1.w};
    uint32_t hi[4], lo[4];
#pragma unroll
    for (int q = 0; q < 4; q++) {
        __nv_bfloat16 h0 = __float2bfloat16_rn(f[2 * q + 0]);
        __nv_bfloat16 h1 = __float2bfloat16_rn(f[2 * q + 1]);
        __nv_bfloat16 l0 = __float2bfloat16_rn(f[2 * q + 0] - __bfloat162float(h0));
        __nv_bfloat16 l1 = __float2bfloat16_rn(f[2 * q + 1] - __bfloat162float(h1));
        hi[q] = (uint32_t)__bfloat16_as_ushort(h0) | ((uint32_t)__bfloat16_as_ushort(h1) << 16);
        lo[q] = (uint32_t)__bfloat16_as_ushort(l0) | ((uint32_t)__bfloat16_as_ushort(l1) << 16);
    }
    uint4 ph = make_uint4(hi[0], hi[1], hi[2], hi[3]);
    uint4 pl = make_uint4(lo[0], lo[1], lo[2], lo[3]);
    reinterpret_cast<uint4*>(g_Ahi)[i] = ph;
    reinterpret_cast<uint4*>(g_Alo)[i] = pl;
}

// ---------------------------------------------------------------------------
// Prep 2: build W_total hi/lo. One thread handles 4 packed int32 (8 weights).
// packed[o][j]: low nibble -> col 2j, high nibble -> col 2j+1, value = nib-8.
// ---------------------------------------------------------------------------
__global__ void prep_w_kernel(const int* __restrict__ packed,
                              const float* __restrict__ scales,
                              const float* __restrict__ ortho) {
    size_t t = (size_t)blockIdx.x * blockDim.x + threadIdx.x; // per 4 packed ints
    if (t >= ((size_t)N_TOT * (K_TOT / 2)) / 4) return;
    int o = (int)(t >> 9);   // (K_TOT/2)/4 = 512 groups per row
    int jj = (int)(t & 511);

    int4 p = reinterpret_cast<const int4*>(packed)[t];
    float inv = 1.0f / __ldg(&scales[o]);
    const float4* orow = reinterpret_cast<const float4*>(ortho + (size_t)o * K_TOT + (size_t)jj * 8);
    float4 t0 = orow[0];
    float4 t1 = orow[1];
    float og[8] = {t0.x, t0.y, t0.z, t0.w, t1.x, t1.y, t1.z, t1.w};
    int pv[4] = {p.x, p.y, p.z, p.w};

    uint32_t hi[4], lo[4];
#pragma unroll
    for (int q = 0; q < 4; q++) {
        float w0 = (float)((pv[q] & 0xF) - 8)        + og[2 * q + 0] * inv;
        float w1 = (float)(((pv[q] >> 4) & 0xF) - 8) + og[2 * q + 1] * inv;
        __nv_bfloat16 h0 = __float2bfloat16_rn(w0);
        __nv_bfloat16 h1 = __float2bfloat16_rn(w1);
        __nv_bfloat16 l0 = __float2bfloat16_rn(w0 - __bfloat162float(h0));
        __nv_bfloat16 l1 = __float2bfloat16_rn(w1 - __bfloat162float(h1));
        hi[q] = (uint32_t)__bfloat16_as_ushort(h0) | ((uint32_t)__bfloat16_as_ushort(h1) << 16);
        lo[q] = (uint32_t)__bfloat16_as_ushort(l0) | ((uint32_t)__bfloat16_as_ushort(l1) << 16);
    }
    reinterpret_cast<uint4*>(g_Whi)[t] = make_uint4(hi[0], hi[1], hi[2], hi[3]);
    reinterpret_cast<uint4*>(g_Wlo)[t] = make_uint4(lo[0], lo[1], lo[2], lo[3]);
}

// ---------------------------------------------------------------------------
// GEMM: out[m][n] = scale[n] * sum over 3 passes of A_p @ B_p^T
// Tile 128x128, BK=64, 256 threads (8 warps, 2x4), mma.sync m16n8k16 bf16.
// SW128 swizzled smem, cp.async double buffer.
// ---------------------------------------------------------------------------
__device__ __forceinline__ void cp_tile(uint32_t s_base, const __nv_bfloat16* g,
                                        int c, int r0) {
#pragma unroll
    for (int i = 0; i < 4; i++) {
        int row = r0 + i * 32;
        const void* src = g + (size_t)row * K_TOT + c * 8;
        uint32_t dst = s_base + row * 128 + (((uint32_t)(c ^ (row & 7))) << 4);
        asm volatile("cp.async.cg.shared.global [%0], [%1], 16;" ::"r"(dst), "l"(src));
    }
}

__global__ void __launch_bounds__(256, 2)
gemm3_kernel(float* __restrict__ out, const float* __restrict__ scales) {
    extern __shared__ __nv_bfloat16 smem[];
    const int tid = threadIdx.x;
    const int lane = tid & 31;
    const int warp = tid >> 5;
    const int wm = warp >> 2;  // 0..1
    const int wn = warp & 3;   // 0..3
    const int bm = blockIdx.y * 128;
    const int bn = blockIdx.x * 128;

    const __nv_bfloat16* Asrc[3] = {g_Ahi, g_Alo, g_Ahi};
    const __nv_bfloat16* Bsrc[3] = {g_Whi, g_Whi, g_Wlo};

    uint32_t sA = (uint32_t)__cvta_generic_to_shared(smem);          // A: 2 x 16KB
    uint32_t sB = sA + 32768;                                        // B: 2 x 16KB

    const int c  = tid & 7;   // 16B chunk within a 128B row
    const int r0 = tid >> 3;  // base row (0..31)

    float acc[4][4][4];
#pragma unroll
    for (int a = 0; a < 4; a++)
#pragma unroll
        for (int b = 0; b < 4; b++)
#pragma unroll
            for (int d = 0; d < 4; d++) acc[a][b][d] = 0.0f;

    // prologue: prefetch chunk 0 into buffer 0
    cp_tile(sA, Asrc[0] + (size_t)bm * K_TOT, c, r0);
    cp_tile(sB, Bsrc[0] + (size_t)bn * K_TOT, c, r0);
    asm volatile("cp.async.commit_group;");

    const int NCH = 3 * (K_TOT / 64);  // 192 k-chunks across 3 passes
    for (int t = 0; t < NCH; ++t) {
        asm volatile("cp.async.wait_group 0;");
        __syncthreads();
        const int buf = t & 1;
        if (t + 1 < NCH) {
            const int tn = t + 1;
            const int pass = tn >> 6;
            const int k0 = (tn & 63) << 6;
            const int nb = tn & 1;
            cp_tile(sA + nb * 16384, Asrc[pass] + (size_t)bm * K_TOT + k0, c, r0);
            cp_tile(sB + nb * 16384, Bsrc[pass] + (size_t)bn * K_TOT + k0, c, r0);
            asm volatile("cp.async.commit_group;");
        }
        const uint32_t aBase = sA + buf * 16384;
        const uint32_t bBase = sB + buf * 16384;
#pragma unroll
        for (int ks = 0; ks < 4; ++ks) {
            uint32_t af[4][4];
            uint32_t bfm[4][2];
            const int chunk = ks * 2 + (lane >> 4);
            const int lrow = lane & 15;
#pragma unroll
            for (int mi = 0; mi < 4; mi++) {
                int row = wm * 64 + mi * 16 + lrow;
                uint32_t addr = aBase + row * 128 + (((uint32_t)(chunk ^ (row & 7))) << 4);
                asm volatile(
                    "ldmatrix.sync.aligned.m8n8.x4.shared.b16 {%0,%1,%2,%3}, [%4];"
                    : "=r"(af[mi][0]), "=r"(af[mi][1]), "=r"(af[mi][2]), "=r"(af[mi][3])
                    : "r"(addr));
            }
#pragma unroll
            for (int np = 0; np < 2; np++) {
                int row = wn * 32 + np * 16 + lrow;
                uint32_t addr = bBase + row * 128 + (((uint32_t)(chunk ^ (row & 7))) << 4);
                uint32_t q0, q1, q2, q3;
                asm volatile(
                    "ldmatrix.sync.aligned.m8n8.x4.shared.b16 {%0,%1,%2,%3}, [%4];"
                    : "=r"(q0), "=r"(q1), "=r"(q2), "=r"(q3)
                    : "r"(addr));
                bfm[np * 2 + 0][0] = q0; bfm[np * 2 + 0][1] = q2;
                bfm[np * 2 + 1][0] = q1; bfm[np * 2 + 1][1] = q3;
            }
#pragma unroll
            for (int mi = 0; mi < 4; mi++)
#pragma unroll
                for (int nt = 0; nt < 4; nt++) {
                    asm volatile(
                        "mma.sync.aligned.m16n8k16.row.col.f32.bf16.bf16.f32 "
                        "{%0,%1,%2,%3}, {%4,%5,%6,%7}, {%8,%9}, {%0,%1,%2,%3};"
                        : "+f"(acc[mi][nt][0]), "+f"(acc[mi][nt][1]),
                          "+f"(acc[mi][nt][2]), "+f"(acc[mi][nt][3])
                        : "r"(af[mi][0]), "r"(af[mi][1]), "r"(af[mi][2]), "r"(af[mi][3]),
                          "r"(bfm[nt][0]), "r"(bfm[nt][1]));
                }
        }
    }

    // epilogue: out = acc * scale[n]
#pragma unroll
    for (int nt = 0; nt < 4; nt++) {
        int col = bn + wn * 32 + nt * 8 + (lane & 3) * 2;
        float s0 = __ldg(&scales[col]);
        float s1 = __ldg(&scales[col + 1]);
#pragma unroll
        for (int mi = 0; mi < 4; mi++) {
            int row = bm + wm * 64 + mi * 16 + (lane >> 2);
            float2* p0 = reinterpret_cast<float2*>(out + (size_t)row * N_TOT + col);
            float2* p1 = reinterpret_cast<float2*>(out + (size_t)(row + 8) * N_TOT + col);
            *p0 = make_float2(acc[mi][nt][0] * s0, acc[mi][nt][1] * s1);
            *p1 = make_float2(acc[mi][nt][2] * s0, acc[mi][nt][3] * s1);
        }
    }
}

// ---------------------------------------------------------------------------
// Launch
// ---------------------------------------------------------------------------
extern "C" void kernel_launch(void* const* d_in, const int* in_sizes, int n_in,
                              void* d_out, int out_size) {
    const float* x      = (const float*)d_in[0];
    const int*   packed = (const int*)d_in[1];
    const float* scales = (const float*)d_in[2];
    const float* ortho  = (const float*)d_in[3];
    float* out = (float*)d_out;

    // x split: 33.5M elems / 8 per thread
    prep_x_kernel<<<(M_TOT * (size_t)K_TOT / 8 + 255) / 256, 256>>>(x);
    // W build: 8.4M packed ints / 4 per thread
    prep_w_kernel<<<((size_t)N_TOT * (K_TOT / 2) / 4 + 255) / 256, 256>>>(packed, scales, ortho);

    cudaFuncSetAttribute(gemm3_kernel, cudaFuncAttributeMaxDynamicSharedMemorySize, 65536);
    dim3 grid(N_TOT / 128, M_TOT / 128);  // (32, 64)
    gemm3_kernel<<<grid, 256, 65536>>>(out, scales);
}